// round 15
// baseline (speedup 1.0000x reference)
#include <cuda_runtime.h>
#include <math.h>

#define BATCH 512
#define NV 6890
#define NBETA 10
#define NJOINT 24

#define ATILE 64
#define NBLKA ((NV + ATILE - 1) / ATILE)   // 108

#define CBLK 128         // kernelC threads
#define VPT 3            // vertices per thread
#define CVERT (CBLK*VPT) // 384 vertices per block
#define NBCH 32          // kernelC batch-chunks
#define BPB (BATCH/NBCH) // 16 batches per block
#define WSTR 26          // sW row stride (floats)

#define VBLK 256         // kernelV threads (= vertices per block)
#define VB_B 16          // kernelV batches per block
#define VCHUNKS ((NV + VBLK - 1) / VBLK)   // 27
#define SDSTR 31         // sd smem row stride (odd -> conflict-free)

#define BWARPS 4         // kernelB batches (warps) per block

__constant__ int c_parents[NJOINT] = {-1,0,0,0,1,2,3,4,5,6,7,8,9,9,9,12,13,14,16,17,18,19,20,21};

// Device scratch (no allocations allowed)
__device__ float  g_part2[NBLKA][NJOINT][33];
__device__ float  g_tot [NJOINT][33];
__device__ float4 g_A4  [BATCH * NJOINT * 3];
__device__ float  g_vs  [(size_t)BATCH * NV * 3];   // v_shaped scratch (42MB)
__device__ unsigned int g_ctrA;                      // zero-init; self-resetting

// ---- f32x2 packed-math helpers --------------------------------------------
__device__ __forceinline__ void f2unpack(unsigned long long v, float& lo, float& hi) {
    asm("mov.b64 {%0, %1}, %2;" : "=f"(lo), "=f"(hi) : "l"(v));
}
__device__ __forceinline__ unsigned long long ffma2(unsigned long long a,
                                                    unsigned long long b,
                                                    unsigned long long c) {
    unsigned long long d;
    asm("fma.rn.f32x2 %0, %1, %2, %3;" : "=l"(d) : "l"(a), "l"(b), "l"(c));
    return d;
}

// ---- cp.async helpers ------------------------------------------------------
__device__ __forceinline__ void cp16(unsigned int dst, const void* src) {
    asm volatile("cp.async.cg.shared.global [%0], [%1], 16;" :: "r"(dst), "l"(src) : "memory");
}
__device__ __forceinline__ void cp_commit() {
    asm volatile("cp.async.commit_group;" ::: "memory");
}
__device__ __forceinline__ void cp_wait1() {
    asm volatile("cp.async.wait_group 1;" ::: "memory");
}
__device__ __forceinline__ void cp_wait0() {
    asm volatile("cp.async.wait_group 0;" ::: "memory");
}

// ---------------------------------------------------------------------------
// Kernel A: joint-regressor partial sums; LAST block reduces into g_tot.
// ---------------------------------------------------------------------------
__global__ void __launch_bounds__(256) kernelA(
    const float* __restrict__ shapedirs,
    const float* __restrict__ v_template,
    const float* __restrict__ Jr)
{
    __shared__ float feat[ATILE][33];
    __shared__ float sJr[NJOINT][ATILE];
    __shared__ unsigned int sIsLast;

    int tid = threadIdx.x;
    int v0 = blockIdx.x * ATILE;

    for (int idx = tid; idx < ATILE * 33; idx += 256) {
        int v = idx / 33, i = idx % 33;
        int gv = v0 + v;
        float val = 0.f;
        if (gv < NV) val = (i < 3) ? v_template[gv * 3 + i]
                                   : shapedirs[(size_t)gv * 30 + (i - 3)];
        feat[v][i] = val;
    }
    for (int idx = tid; idx < NJOINT * ATILE; idx += 256) {
        int j = idx / ATILE, v = idx % ATILE;
        int gv = v0 + v;
        sJr[j][v] = (gv < NV) ? Jr[j * NV + gv] : 0.f;
    }
    __syncthreads();

    int warp = tid >> 5, lane = tid & 31;
#pragma unroll
    for (int jj = 0; jj < 3; jj++) {
        int j = warp * 3 + jj;
        for (int i = lane; i < 33; i += 32) {
            float a0 = 0.f, a1 = 0.f, a2 = 0.f, a3 = 0.f;
#pragma unroll
            for (int v = 0; v < ATILE; v += 4) {
                a0 = fmaf(sJr[j][v + 0], feat[v + 0][i], a0);
                a1 = fmaf(sJr[j][v + 1], feat[v + 1][i], a1);
                a2 = fmaf(sJr[j][v + 2], feat[v + 2][i], a2);
                a3 = fmaf(sJr[j][v + 3], feat[v + 3][i], a3);
            }
            g_part2[blockIdx.x][j][i] = (a0 + a1) + (a2 + a3);
        }
    }

    __threadfence();
    __syncthreads();
    if (tid == 0)
        sIsLast = (atomicAdd(&g_ctrA, 1u) == (unsigned)(NBLKA - 1));
    __syncthreads();
    if (sIsLast) {
        for (int t = tid; t < NJOINT * 33; t += 256) {
            int j = t / 33, i33 = t % 33;
            int src;
            if (i33 % 11 == 0) src = i33 / 11;
            else { int k = i33 / 11, l = i33 % 11 - 1; src = 3 + k * 10 + l; }
            float s0 = 0.f, s1 = 0.f, s2 = 0.f, s3 = 0.f;
            for (int c = 0; c < NBLKA; c += 4) {
                s0 += g_part2[c + 0][j][src];
                s1 += g_part2[c + 1][j][src];
                s2 += g_part2[c + 2][j][src];
                s3 += g_part2[c + 3][j][src];
            }
            g_tot[j][i33] = (s0 + s1) + (s2 + s3);
        }
        if (tid == 0) g_ctrA = 0;
    }
}

// ---------------------------------------------------------------------------
// Kernel V: v_shaped precompute with coalesced smem staging of shapedirs.
// Block owns 256 vertices x VB_B batches; sd lives in smem (stride-31 rows).
// ---------------------------------------------------------------------------
__global__ void __launch_bounds__(VBLK, 4) kernelV(
    const float* __restrict__ betas,
    const float* __restrict__ shapedirs,
    const float* __restrict__ v_template)
{
    __shared__ float sSD[VBLK * SDSTR];   // 31 KB
    __shared__ float sVT[VBLK * 3];
    __shared__ float sB[VB_B][11];

    int tid = threadIdx.x;
    int v0 = blockIdx.x * VBLK;
    int b0 = blockIdx.y * VB_B;
    int nv_blk = min(VBLK, NV - v0);

    // coalesced stage of shapedirs span [v0*30, (v0+nv_blk)*30)
    {
        const float* src = shapedirs + (size_t)v0 * 30;
        int limit = nv_blk * 30;
        for (int i = tid; i < limit; i += VBLK)
            sSD[(i / 30) * SDSTR + (i % 30)] = src[i];
    }
    {
        const float* src = v_template + (size_t)v0 * 3;
        int limit = nv_blk * 3;
        for (int i = tid; i < limit; i += VBLK)
            sVT[i] = src[i];
    }
    for (int i = tid; i < VB_B * 11; i += VBLK)
        sB[i / 11][i % 11] = betas[(b0 + i / 11) * 11 + i % 11];
    __syncthreads();

    int v = v0 + tid;
    if (v >= NV) return;

    const float* sd = sSD + tid * SDSTR;
    float vt0 = sVT[tid * 3 + 0];
    float vt1 = sVT[tid * 3 + 1];
    float vt2 = sVT[tid * 3 + 2];

#pragma unroll 4
    for (int i = 0; i < VB_B; i++) {
        int b = b0 + i;
        const float* BT = sB[i];
        float be0 = BT[0];
        float q0 = vt0, q1 = vt1, q2 = vt2;
#pragma unroll
        for (int l = 0; l < NBETA; l++) {
            float bl = BT[1 + l];
            q0 = fmaf(bl, sd[l],      q0);
            q1 = fmaf(bl, sd[10 + l], q1);
            q2 = fmaf(bl, sd[20 + l], q2);
        }
        size_t base = ((size_t)b * NV + v) * 3;
        g_vs[base + 0] = q0 * be0;
        g_vs[base + 1] = q1 * be0;
        g_vs[base + 2] = q2 * be0;
    }
}

// ---------------------------------------------------------------------------
// Kernel B: 4 batches per block (1 warp each); g_tot staged in shared;
// kinematic chain 2 joints per pass.
// ---------------------------------------------------------------------------
__global__ void __launch_bounds__(BWARPS * 32) kernelB(
    const float* __restrict__ betas,
    const float* __restrict__ body_pose,
    const float* __restrict__ global_or,
    float* __restrict__ d_out)
{
    int wid = threadIdx.x >> 5;
    int lane = threadIdx.x & 31;
    int b = blockIdx.x * BWARPS + wid;

    __shared__ float sTot[NJOINT][33];
    __shared__ float sB[BWARPS][11];
    __shared__ float sLoc[BWARPS][NJOINT][12];
    __shared__ float sWorld[BWARPS][NJOINT][12];
    __shared__ float sJ[BWARPS][NJOINT][3];

    for (int idx = threadIdx.x; idx < NJOINT * 33; idx += BWARPS * 32)
        ((float*)sTot)[idx] = ((const float*)g_tot)[idx];
    if (lane < 11) sB[wid][lane] = betas[b * 11 + lane];
    __syncthreads();

    if (lane < NJOINT) {
        int j = lane;
        float s0 = sB[wid][0];
#pragma unroll
        for (int k = 0; k < 3; k++) {
            float val = sTot[j][k * 11];
#pragma unroll
            for (int l = 0; l < NBETA; l++)
                val += sB[wid][1 + l] * sTot[j][k * 11 + 1 + l];
            sJ[wid][j][k] = val * s0;
        }
    }
    __syncwarp();

    if (lane < NJOINT) {
        int j = lane;
        float r0, r1, r2;
        if (j == 0) {
            r0 = global_or[b * 3 + 0]; r1 = global_or[b * 3 + 1]; r2 = global_or[b * 3 + 2];
        } else {
            const float* pp = body_pose + b * 69 + (j - 1) * 3;
            r0 = pp[0]; r1 = pp[1]; r2 = pp[2];
        }
        float a0 = r0 + 1e-8f, a1 = r1 + 1e-8f, a2 = r2 + 1e-8f;
        float angle = __fsqrt_rn(a0 * a0 + a1 * a1 + a2 * a2);
        float inv = __frcp_rn(angle);
        float rx = r0 * inv, ry = r1 * inv, rz = r2 * inv;
        float c = __cosf(angle), s = __sinf(angle), t = 1.f - c;
        sLoc[wid][j][0]  = 1.f - t * (ry * ry + rz * rz);
        sLoc[wid][j][1]  = -s * rz + t * rx * ry;
        sLoc[wid][j][2]  =  s * ry + t * rx * rz;
        sLoc[wid][j][4]  =  s * rz + t * rx * ry;
        sLoc[wid][j][5]  = 1.f - t * (rx * rx + rz * rz);
        sLoc[wid][j][6]  = -s * rx + t * ry * rz;
        sLoc[wid][j][8]  = -s * ry + t * rx * rz;
        sLoc[wid][j][9]  =  s * rx + t * ry * rz;
        sLoc[wid][j][10] = 1.f - t * (rx * rx + ry * ry);
        int p = c_parents[j];
#pragma unroll
        for (int k = 0; k < 3; k++)
            sLoc[wid][j][k * 4 + 3] = (p < 0) ? sJ[wid][j][k]
                                              : (sJ[wid][j][k] - sJ[wid][p][k]);
    }
    __syncwarp();

    if (lane < 12) sWorld[wid][0][lane] = sLoc[wid][0][lane];
    __syncwarp();
    for (int j = 1; j < NJOINT; j += 2) {
        int jj = j + (lane >= 12 ? 1 : 0);
        int l12 = (lane >= 12) ? (lane - 12) : lane;
        if (lane < 24 && jj < NJOINT) {
            int r = l12 >> 2, cc = l12 & 3;
            int p = c_parents[jj];
            float val = sWorld[wid][p][r * 4 + 0] * sLoc[wid][jj][0 * 4 + cc]
                      + sWorld[wid][p][r * 4 + 1] * sLoc[wid][jj][1 * 4 + cc]
                      + sWorld[wid][p][r * 4 + 2] * sLoc[wid][jj][2 * 4 + cc];
            if (cc == 3) val += sWorld[wid][p][r * 4 + 3];
            sWorld[wid][jj][l12] = val;
        }
        __syncwarp();
    }

    float* Jout = d_out + (size_t)BATCH * NV * 3;
    if (lane < NJOINT) {
        int j = lane;
        float jx = sJ[wid][j][0], jy = sJ[wid][j][1], jz = sJ[wid][j][2];
        float* Aout = (float*)g_A4 + (size_t)b * 288 + j * 12;
#pragma unroll
        for (int r = 0; r < 3; r++) {
            float m0 = sWorld[wid][j][r * 4 + 0];
            float m1 = sWorld[wid][j][r * 4 + 1];
            float m2 = sWorld[wid][j][r * 4 + 2];
            float m3 = sWorld[wid][j][r * 4 + 3];
            Jout[(size_t)b * NJOINT * 3 + j * 3 + r] = m3;
            Aout[r * 4 + 0] = m0;
            Aout[r * 4 + 1] = m1;
            Aout[r * 4 + 2] = m2;
            Aout[r * 4 + 3] = m3 - (m0 * jx + m1 * jy + m2 * jz);
        }
    }
}

// ---------------------------------------------------------------------------
// Kernel C: LBS, VPT=3 — A-broadcast LDS amortized over 3 vertices.
// ---------------------------------------------------------------------------
__global__ void __launch_bounds__(CBLK, 4) kernelC(
    const float* __restrict__ transl,      // [B,3]
    const float* __restrict__ W,           // [V,24]
    float* __restrict__ out)               // verts [B,V,3]
{
    __shared__ float4 sAw[CBLK / 32][2][NJOINT * 3];
    __shared__ float  sTr[BPB][3];
    __shared__ float  sW[CVERT * WSTR];

    int tid = threadIdx.x;
    int lane = tid & 31;
    int w = tid >> 5;
    int b0 = blockIdx.y * BPB;

    int v0 = blockIdx.x * CVERT + tid;
    int v1 = v0 + CBLK;
    int v2 = v0 + 2 * CBLK;
    bool valid0 = (v0 < NV), valid1 = (v1 < NV), valid2 = (v2 < NV);
    int vc0 = valid0 ? v0 : (NV - 1);
    int vc1 = valid1 ? v1 : (NV - 1);
    int vc2 = valid2 ? v2 : (NV - 1);

    for (int idx = tid; idx < BPB * 3; idx += CBLK)
        sTr[idx / 3][idx % 3] = transl[(b0 + idx / 3) * 3 + idx % 3];

    {
        const float4* Wp0 = (const float4*)(W + (size_t)vc0 * NJOINT);
        const float4* Wp1 = (const float4*)(W + (size_t)vc1 * NJOINT);
        const float4* Wp2 = (const float4*)(W + (size_t)vc2 * NJOINT);
        float* r0 = sW + tid * WSTR;
        float* r1 = sW + (tid + CBLK) * WSTR;
        float* r2 = sW + (tid + 2 * CBLK) * WSTR;
#pragma unroll
        for (int q = 0; q < 6; q++) {
            float4 t4 = Wp0[q];
            r0[4*q+0] = t4.x; r0[4*q+1] = t4.y; r0[4*q+2] = t4.z; r0[4*q+3] = t4.w;
            float4 u4 = Wp1[q];
            r1[4*q+0] = u4.x; r1[4*q+1] = u4.y; r1[4*q+2] = u4.z; r1[4*q+3] = u4.w;
            float4 s4 = Wp2[q];
            r2[4*q+0] = s4.x; r2[4*q+1] = s4.y; r2[4*q+2] = s4.z; r2[4*q+3] = s4.w;
        }
    }

    unsigned int sbase = (unsigned int)__cvta_generic_to_shared(&sAw[w][0][0]);
    const float4* Ag = g_A4;
    {
        const float4* s0 = Ag + (size_t)b0 * 72 + lane;
        unsigned int d = sbase + lane * 16;
        cp16(d, s0); cp16(d + 32 * 16, s0 + 32);
        if (lane < 8) cp16(d + 64 * 16, s0 + 64);
        cp_commit();
        const float4* s1 = Ag + (size_t)(b0 + 1) * 72 + lane;
        unsigned int d1 = d + 72 * 16;
        cp16(d1, s1); cp16(d1 + 32 * 16, s1 + 32);
        if (lane < 8) cp16(d1 + 64 * 16, s1 + 64);
        cp_commit();
    }
    __syncthreads();

    float pA0, pA1, pA2, pB0, pB1, pB2, pC0, pC1, pC2;
    {
        const float* p = g_vs + ((size_t)b0 * NV + vc0) * 3;
        pA0 = p[0]; pA1 = p[1]; pA2 = p[2];
        const float* q = g_vs + ((size_t)b0 * NV + vc1) * 3;
        pB0 = q[0]; pB1 = q[1]; pB2 = q[2];
        const float* r = g_vs + ((size_t)b0 * NV + vc2) * 3;
        pC0 = r[0]; pC1 = r[1]; pC2 = r[2];
    }

    const float2* wr0 = (const float2*)(sW + tid * WSTR);
    const float2* wr1 = (const float2*)(sW + (tid + CBLK) * WSTR);
    const float2* wr2 = (const float2*)(sW + (tid + 2 * CBLK) * WSTR);

    for (int ib = 0; ib < BPB; ib++) {
        if (ib >= BPB - 2) cp_wait0(); else cp_wait1();
        __syncwarp();

        int cur = ib & 1;
        const ulonglong2* A2 = (const ulonglong2*)&sAw[w][cur][0];

        unsigned long long TA0=0,TA1=0,TA2=0,TA3=0,TA4=0,TA5=0;
        unsigned long long TB0=0,TB1=0,TB2=0,TB3=0,TB4=0,TB5=0;
        unsigned long long TC0=0,TC1=0,TC2=0,TC3=0,TC4=0,TC5=0;
#pragma unroll
        for (int np = 0; np < NJOINT / 2; np++) {
            float2 wA2 = wr0[np];
            float2 wB2 = wr1[np];
            float2 wC2 = wr2[np];
#pragma unroll
            for (int h = 0; h < 2; h++) {
                int n = 2 * np + h;
                float wA = h ? wA2.y : wA2.x;
                float wB = h ? wB2.y : wB2.x;
                float wC = h ? wC2.y : wC2.x;
                unsigned long long wpA, wpB, wpC;
                asm volatile("mov.b64 %0, {%1, %1};" : "=l"(wpA) : "f"(wA));
                asm volatile("mov.b64 %0, {%1, %1};" : "=l"(wpB) : "f"(wB));
                asm volatile("mov.b64 %0, {%1, %1};" : "=l"(wpC) : "f"(wC));
                ulonglong2 a0 = A2[n * 3 + 0];
                ulonglong2 a1 = A2[n * 3 + 1];
                ulonglong2 a2 = A2[n * 3 + 2];
                TA0 = ffma2(wpA, a0.x, TA0); TB0 = ffma2(wpB, a0.x, TB0); TC0 = ffma2(wpC, a0.x, TC0);
                TA1 = ffma2(wpA, a0.y, TA1); TB1 = ffma2(wpB, a0.y, TB1); TC1 = ffma2(wpC, a0.y, TC1);
                TA2 = ffma2(wpA, a1.x, TA2); TB2 = ffma2(wpB, a1.x, TB2); TC2 = ffma2(wpC, a1.x, TC2);
                TA3 = ffma2(wpA, a1.y, TA3); TB3 = ffma2(wpB, a1.y, TB3); TC3 = ffma2(wpC, a1.y, TC3);
                TA4 = ffma2(wpA, a2.x, TA4); TB4 = ffma2(wpB, a2.x, TB4); TC4 = ffma2(wpC, a2.x, TC4);
                TA5 = ffma2(wpA, a2.y, TA5); TB5 = ffma2(wpB, a2.y, TB5); TC5 = ffma2(wpC, a2.y, TC5);
            }
        }

        int b = b0 + ib;
        float tr0 = sTr[ib][0], tr1 = sTr[ib][1], tr2 = sTr[ib][2];

        if (valid0) {
            float t00,t01,t02,t03,t10,t11,t12,t13,t20,t21,t22,t23;
            f2unpack(TA0,t00,t01); f2unpack(TA1,t02,t03);
            f2unpack(TA2,t10,t11); f2unpack(TA3,t12,t13);
            f2unpack(TA4,t20,t21); f2unpack(TA5,t22,t23);
            size_t base = ((size_t)b * NV + v0) * 3;
            out[base+0] = fmaf(t00,pA0, fmaf(t01,pA1, fmaf(t02,pA2, t03 + tr0)));
            out[base+1] = fmaf(t10,pA0, fmaf(t11,pA1, fmaf(t12,pA2, t13 + tr1)));
            out[base+2] = fmaf(t20,pA0, fmaf(t21,pA1, fmaf(t22,pA2, t23 + tr2)));
        }
        if (valid1) {
            float t00,t01,t02,t03,t10,t11,t12,t13,t20,t21,t22,t23;
            f2unpack(TB0,t00,t01); f2unpack(TB1,t02,t03);
            f2unpack(TB2,t10,t11); f2unpack(TB3,t12,t13);
            f2unpack(TB4,t20,t21); f2unpack(TB5,t22,t23);
            size_t base = ((size_t)b * NV + v1) * 3;
            out[base+0] = fmaf(t00,pB0, fmaf(t01,pB1, fmaf(t02,pB2, t03 + tr0)));
            out[base+1] = fmaf(t10,pB0, fmaf(t11,pB1, fmaf(t12,pB2, t13 + tr1)));
            out[base+2] = fmaf(t20,pB0, fmaf(t21,pB1, fmaf(t22,pB2, t23 + tr2)));
        }
        if (valid2) {
            float t00,t01,t02,t03,t10,t11,t12,t13,t20,t21,t22,t23;
            f2unpack(TC0,t00,t01); f2unpack(TC1,t02,t03);
            f2unpack(TC2,t10,t11); f2unpack(TC3,t12,t13);
            f2unpack(TC4,t20,t21); f2unpack(TC5,t22,t23);
            size_t base = ((size_t)b * NV + v2) * 3;
            out[base+0] = fmaf(t00,pC0, fmaf(t01,pC1, fmaf(t02,pC2, t03 + tr0)));
            out[base+1] = fmaf(t10,pC0, fmaf(t11,pC1, fmaf(t12,pC2, t13 + tr1)));
            out[base+2] = fmaf(t20,pC0, fmaf(t21,pC1, fmaf(t22,pC2, t23 + tr2)));
        }

        if (ib + 1 < BPB) {
            const float* p = g_vs + ((size_t)(b + 1) * NV + vc0) * 3;
            pA0 = p[0]; pA1 = p[1]; pA2 = p[2];
            const float* q = g_vs + ((size_t)(b + 1) * NV + vc1) * 3;
            pB0 = q[0]; pB1 = q[1]; pB2 = q[2];
            const float* r = g_vs + ((size_t)(b + 1) * NV + vc2) * 3;
            pC0 = r[0]; pC1 = r[1]; pC2 = r[2];
        }

        if (ib + 2 < BPB) {
            const float4* sn = Ag + (size_t)(b + 2) * 72 + lane;
            unsigned int d = sbase + cur * (72 * 16) + lane * 16;
            cp16(d, sn); cp16(d + 32 * 16, sn + 32);
            if (lane < 8) cp16(d + 64 * 16, sn + 64);
            cp_commit();
        }
    }
}

extern "C" void kernel_launch(void* const* d_in, const int* in_sizes, int n_in,
                              void* d_out, int out_size)
{
    const float* betas      = (const float*)d_in[0];
    const float* body_pose  = (const float*)d_in[1];
    const float* global_or  = (const float*)d_in[2];
    const float* transl     = (const float*)d_in[3];
    const float* shapedirs  = (const float*)d_in[4];
    const float* v_template = (const float*)d_in[5];
    const float* Jr         = (const float*)d_in[6];
    const float* W          = (const float*)d_in[7];
    float* out = (float*)d_out;

    kernelA<<<NBLKA, 256>>>(shapedirs, v_template, Jr);
    dim3 gridV(VCHUNKS, BATCH / VB_B);
    kernelV<<<gridV, VBLK>>>(betas, shapedirs, v_template);
    kernelB<<<BATCH / BWARPS, BWARPS * 32>>>(betas, body_pose, global_or, out);
    dim3 gridC((NV + CVERT - 1) / CVERT, NBCH);
    kernelC<<<gridC, CBLK>>>(transl, W, out);
}

// round 16
// speedup vs baseline: 1.1128x; 1.1128x over previous
#include <cuda_runtime.h>
#include <math.h>

#define BATCH 512
#define NV 6890
#define NBETA 10
#define NJOINT 24

#define ATILE 64
#define NBLKA ((NV + ATILE - 1) / ATILE)   // 108

#define CBLK 128         // kernelC threads
#define VPT 3            // vertices per thread
#define CVERT (CBLK*VPT) // 384 vertices per block
#define NBCH 32          // kernelC batch-chunks
#define BPB (BATCH/NBCH) // 16 batches per block
#define WSTR 26          // sW row stride (floats)

#define VBLK 256         // V-path vertices per block (= block size)
#define VB_B 16          // V-path batches per block
#define VCHUNKS ((NV + VBLK - 1) / VBLK)   // 27
#define VBLKS (VCHUNKS * (BATCH / VB_B))   // 27*32 = 864
#define SDSTR 31         // sd smem row stride (odd -> conflict-free)

#define BWARPS 4         // kernelB batches (warps) per block

__constant__ int c_parents[NJOINT] = {-1,0,0,0,1,2,3,4,5,6,7,8,9,9,9,12,13,14,16,17,18,19,20,21};

// Device scratch (no allocations allowed)
__device__ float  g_part2[NBLKA][NJOINT][33];
__device__ float  g_tot [NJOINT][33];
__device__ float4 g_A4  [BATCH * NJOINT * 3];
__device__ float  g_vs  [(size_t)BATCH * NV * 3];   // v_shaped scratch (42MB)
__device__ unsigned int g_ctrA;                      // zero-init; self-resetting

// ---- f32x2 packed-math helpers --------------------------------------------
__device__ __forceinline__ void f2unpack(unsigned long long v, float& lo, float& hi) {
    asm("mov.b64 {%0, %1}, %2;" : "=f"(lo), "=f"(hi) : "l"(v));
}
__device__ __forceinline__ unsigned long long ffma2(unsigned long long a,
                                                    unsigned long long b,
                                                    unsigned long long c) {
    unsigned long long d;
    asm("fma.rn.f32x2 %0, %1, %2, %3;" : "=l"(d) : "l"(a), "l"(b), "l"(c));
    return d;
}

// ---- cp.async helpers ------------------------------------------------------
__device__ __forceinline__ void cp16(unsigned int dst, const void* src) {
    asm volatile("cp.async.cg.shared.global [%0], [%1], 16;" :: "r"(dst), "l"(src) : "memory");
}
__device__ __forceinline__ void cp_commit() {
    asm volatile("cp.async.commit_group;" ::: "memory");
}
__device__ __forceinline__ void cp_wait1() {
    asm volatile("cp.async.wait_group 1;" ::: "memory");
}
__device__ __forceinline__ void cp_wait0() {
    asm volatile("cp.async.wait_group 0;" ::: "memory");
}

// ---------------------------------------------------------------------------
// Kernel AV: fused A (blocks 0..NBLKA-1, + last-block g_tot reduction) and
// V (blocks NBLKA.., coalesced smem-staged shapedirs — no sd register array).
// ---------------------------------------------------------------------------
// smem: A needs 64*33 + 24*64 = 3648 floats; V needs 256*31 + 256*3 + 16*11
// = 8880 floats. Union buffer sized for V.
#define AV_SMEM 8880

__global__ void __launch_bounds__(256) kernelAV(
    const float* __restrict__ shapedirs,
    const float* __restrict__ v_template,
    const float* __restrict__ Jr,
    const float* __restrict__ betas)
{
    __shared__ float smem_u[AV_SMEM];
    __shared__ unsigned int sIsLast;

    int tid = threadIdx.x;

    if (blockIdx.x < NBLKA) {
        // ---------------- A body ----------------
        float (*feat)[33] = (float (*)[33])smem_u;
        float (*sJr)[ATILE] = (float (*)[ATILE])(smem_u + ATILE * 33);
        int v0 = blockIdx.x * ATILE;

        for (int idx = tid; idx < ATILE * 33; idx += 256) {
            int v = idx / 33, i = idx % 33;
            int gv = v0 + v;
            float val = 0.f;
            if (gv < NV) val = (i < 3) ? v_template[gv * 3 + i]
                                       : shapedirs[(size_t)gv * 30 + (i - 3)];
            feat[v][i] = val;
        }
        for (int idx = tid; idx < NJOINT * ATILE; idx += 256) {
            int j = idx / ATILE, v = idx % ATILE;
            int gv = v0 + v;
            sJr[j][v] = (gv < NV) ? Jr[j * NV + gv] : 0.f;
        }
        __syncthreads();

        int warp = tid >> 5, lane = tid & 31;
#pragma unroll
        for (int jj = 0; jj < 3; jj++) {
            int j = warp * 3 + jj;
            for (int i = lane; i < 33; i += 32) {
                float a0 = 0.f, a1 = 0.f, a2 = 0.f, a3 = 0.f;
#pragma unroll
                for (int v = 0; v < ATILE; v += 4) {
                    a0 = fmaf(sJr[j][v + 0], feat[v + 0][i], a0);
                    a1 = fmaf(sJr[j][v + 1], feat[v + 1][i], a1);
                    a2 = fmaf(sJr[j][v + 2], feat[v + 2][i], a2);
                    a3 = fmaf(sJr[j][v + 3], feat[v + 3][i], a3);
                }
                g_part2[blockIdx.x][j][i] = (a0 + a1) + (a2 + a3);
            }
        }

        // last-A-block reduction
        __threadfence();
        __syncthreads();
        if (tid == 0)
            sIsLast = (atomicAdd(&g_ctrA, 1u) == (unsigned)(NBLKA - 1));
        __syncthreads();
        if (sIsLast) {
            for (int t = tid; t < NJOINT * 33; t += 256) {
                int j = t / 33, i33 = t % 33;
                int src;
                if (i33 % 11 == 0) src = i33 / 11;
                else { int k = i33 / 11, l = i33 % 11 - 1; src = 3 + k * 10 + l; }
                float s0 = 0.f, s1 = 0.f, s2 = 0.f, s3 = 0.f;
                for (int c = 0; c < NBLKA; c += 4) {
                    s0 += g_part2[c + 0][j][src];
                    s1 += g_part2[c + 1][j][src];
                    s2 += g_part2[c + 2][j][src];
                    s3 += g_part2[c + 3][j][src];
                }
                g_tot[j][i33] = (s0 + s1) + (s2 + s3);
            }
            if (tid == 0) g_ctrA = 0;
        }
    } else {
        // ---------------- V body (coalesced smem staging) ----------------
        float* sSD = smem_u;                       // 256*31
        float* sVT = smem_u + VBLK * SDSTR;        // 256*3
        float (*sB)[11] = (float (*)[11])(sVT + VBLK * 3);  // 16*11

        int vb = blockIdx.x - NBLKA;
        int vx = vb % VCHUNKS;
        int b0 = (vb / VCHUNKS) * VB_B;
        int v0 = vx * VBLK;
        int nv_blk = min(VBLK, NV - v0);

        {
            const float* src = shapedirs + (size_t)v0 * 30;
            int limit = nv_blk * 30;
            for (int i = tid; i < limit; i += VBLK)
                sSD[(i / 30) * SDSTR + (i % 30)] = src[i];
        }
        {
            const float* src = v_template + (size_t)v0 * 3;
            int limit = nv_blk * 3;
            for (int i = tid; i < limit; i += VBLK)
                sVT[i] = src[i];
        }
        for (int i = tid; i < VB_B * 11; i += VBLK)
            sB[i / 11][i % 11] = betas[(b0 + i / 11) * 11 + i % 11];
        __syncthreads();

        int v = v0 + tid;
        if (v >= NV) return;

        const float* sd = sSD + tid * SDSTR;
        float vt0 = sVT[tid * 3 + 0];
        float vt1 = sVT[tid * 3 + 1];
        float vt2 = sVT[tid * 3 + 2];

#pragma unroll 4
        for (int i = 0; i < VB_B; i++) {
            int b = b0 + i;
            const float* BT = sB[i];
            float be0 = BT[0];
            float q0 = vt0, q1 = vt1, q2 = vt2;
#pragma unroll
            for (int l = 0; l < NBETA; l++) {
                float bl = BT[1 + l];
                q0 = fmaf(bl, sd[l],      q0);
                q1 = fmaf(bl, sd[10 + l], q1);
                q2 = fmaf(bl, sd[20 + l], q2);
            }
            size_t base = ((size_t)b * NV + v) * 3;
            g_vs[base + 0] = q0 * be0;
            g_vs[base + 1] = q1 * be0;
            g_vs[base + 2] = q2 * be0;
        }
    }
}

// ---------------------------------------------------------------------------
// Kernel B: 4 batches per block (1 warp each); g_tot staged in shared;
// kinematic chain 2 joints per pass.
// ---------------------------------------------------------------------------
__global__ void __launch_bounds__(BWARPS * 32) kernelB(
    const float* __restrict__ betas,
    const float* __restrict__ body_pose,
    const float* __restrict__ global_or,
    float* __restrict__ d_out)
{
    int wid = threadIdx.x >> 5;
    int lane = threadIdx.x & 31;
    int b = blockIdx.x * BWARPS + wid;

    __shared__ float sTot[NJOINT][33];
    __shared__ float sB[BWARPS][11];
    __shared__ float sLoc[BWARPS][NJOINT][12];
    __shared__ float sWorld[BWARPS][NJOINT][12];
    __shared__ float sJ[BWARPS][NJOINT][3];

    for (int idx = threadIdx.x; idx < NJOINT * 33; idx += BWARPS * 32)
        ((float*)sTot)[idx] = ((const float*)g_tot)[idx];
    if (lane < 11) sB[wid][lane] = betas[b * 11 + lane];
    __syncthreads();

    if (lane < NJOINT) {
        int j = lane;
        float s0 = sB[wid][0];
#pragma unroll
        for (int k = 0; k < 3; k++) {
            float val = sTot[j][k * 11];
#pragma unroll
            for (int l = 0; l < NBETA; l++)
                val += sB[wid][1 + l] * sTot[j][k * 11 + 1 + l];
            sJ[wid][j][k] = val * s0;
        }
    }
    __syncwarp();

    if (lane < NJOINT) {
        int j = lane;
        float r0, r1, r2;
        if (j == 0) {
            r0 = global_or[b * 3 + 0]; r1 = global_or[b * 3 + 1]; r2 = global_or[b * 3 + 2];
        } else {
            const float* pp = body_pose + b * 69 + (j - 1) * 3;
            r0 = pp[0]; r1 = pp[1]; r2 = pp[2];
        }
        float a0 = r0 + 1e-8f, a1 = r1 + 1e-8f, a2 = r2 + 1e-8f;
        float angle = __fsqrt_rn(a0 * a0 + a1 * a1 + a2 * a2);
        float inv = __frcp_rn(angle);
        float rx = r0 * inv, ry = r1 * inv, rz = r2 * inv;
        float c = __cosf(angle), s = __sinf(angle), t = 1.f - c;
        sLoc[wid][j][0]  = 1.f - t * (ry * ry + rz * rz);
        sLoc[wid][j][1]  = -s * rz + t * rx * ry;
        sLoc[wid][j][2]  =  s * ry + t * rx * rz;
        sLoc[wid][j][4]  =  s * rz + t * rx * ry;
        sLoc[wid][j][5]  = 1.f - t * (rx * rx + rz * rz);
        sLoc[wid][j][6]  = -s * rx + t * ry * rz;
        sLoc[wid][j][8]  = -s * ry + t * rx * rz;
        sLoc[wid][j][9]  =  s * rx + t * ry * rz;
        sLoc[wid][j][10] = 1.f - t * (rx * rx + ry * ry);
        int p = c_parents[j];
#pragma unroll
        for (int k = 0; k < 3; k++)
            sLoc[wid][j][k * 4 + 3] = (p < 0) ? sJ[wid][j][k]
                                              : (sJ[wid][j][k] - sJ[wid][p][k]);
    }
    __syncwarp();

    if (lane < 12) sWorld[wid][0][lane] = sLoc[wid][0][lane];
    __syncwarp();
    for (int j = 1; j < NJOINT; j += 2) {
        int jj = j + (lane >= 12 ? 1 : 0);
        int l12 = (lane >= 12) ? (lane - 12) : lane;
        if (lane < 24 && jj < NJOINT) {
            int r = l12 >> 2, cc = l12 & 3;
            int p = c_parents[jj];
            float val = sWorld[wid][p][r * 4 + 0] * sLoc[wid][jj][0 * 4 + cc]
                      + sWorld[wid][p][r * 4 + 1] * sLoc[wid][jj][1 * 4 + cc]
                      + sWorld[wid][p][r * 4 + 2] * sLoc[wid][jj][2 * 4 + cc];
            if (cc == 3) val += sWorld[wid][p][r * 4 + 3];
            sWorld[wid][jj][l12] = val;
        }
        __syncwarp();
    }

    float* Jout = d_out + (size_t)BATCH * NV * 3;
    if (lane < NJOINT) {
        int j = lane;
        float jx = sJ[wid][j][0], jy = sJ[wid][j][1], jz = sJ[wid][j][2];
        float* Aout = (float*)g_A4 + (size_t)b * 288 + j * 12;
#pragma unroll
        for (int r = 0; r < 3; r++) {
            float m0 = sWorld[wid][j][r * 4 + 0];
            float m1 = sWorld[wid][j][r * 4 + 1];
            float m2 = sWorld[wid][j][r * 4 + 2];
            float m3 = sWorld[wid][j][r * 4 + 3];
            Jout[(size_t)b * NJOINT * 3 + j * 3 + r] = m3;
            Aout[r * 4 + 0] = m0;
            Aout[r * 4 + 1] = m1;
            Aout[r * 4 + 2] = m2;
            Aout[r * 4 + 3] = m3 - (m0 * jx + m1 * jy + m2 * jz);
        }
    }
}

// ---------------------------------------------------------------------------
// Kernel C: LBS, VPT=3 — A-broadcast LDS amortized over 3 vertices.
// ---------------------------------------------------------------------------
__global__ void __launch_bounds__(CBLK, 4) kernelC(
    const float* __restrict__ transl,      // [B,3]
    const float* __restrict__ W,           // [V,24]
    float* __restrict__ out)               // verts [B,V,3]
{
    __shared__ float4 sAw[CBLK / 32][2][NJOINT * 3];
    __shared__ float  sTr[BPB][3];
    __shared__ float  sW[CVERT * WSTR];

    int tid = threadIdx.x;
    int lane = tid & 31;
    int w = tid >> 5;
    int b0 = blockIdx.y * BPB;

    int v0 = blockIdx.x * CVERT + tid;
    int v1 = v0 + CBLK;
    int v2 = v0 + 2 * CBLK;
    bool valid0 = (v0 < NV), valid1 = (v1 < NV), valid2 = (v2 < NV);
    int vc0 = valid0 ? v0 : (NV - 1);
    int vc1 = valid1 ? v1 : (NV - 1);
    int vc2 = valid2 ? v2 : (NV - 1);

    for (int idx = tid; idx < BPB * 3; idx += CBLK)
        sTr[idx / 3][idx % 3] = transl[(b0 + idx / 3) * 3 + idx % 3];

    {
        const float4* Wp0 = (const float4*)(W + (size_t)vc0 * NJOINT);
        const float4* Wp1 = (const float4*)(W + (size_t)vc1 * NJOINT);
        const float4* Wp2 = (const float4*)(W + (size_t)vc2 * NJOINT);
        float* r0 = sW + tid * WSTR;
        float* r1 = sW + (tid + CBLK) * WSTR;
        float* r2 = sW + (tid + 2 * CBLK) * WSTR;
#pragma unroll
        for (int q = 0; q < 6; q++) {
            float4 t4 = Wp0[q];
            r0[4*q+0] = t4.x; r0[4*q+1] = t4.y; r0[4*q+2] = t4.z; r0[4*q+3] = t4.w;
            float4 u4 = Wp1[q];
            r1[4*q+0] = u4.x; r1[4*q+1] = u4.y; r1[4*q+2] = u4.z; r1[4*q+3] = u4.w;
            float4 s4 = Wp2[q];
            r2[4*q+0] = s4.x; r2[4*q+1] = s4.y; r2[4*q+2] = s4.z; r2[4*q+3] = s4.w;
        }
    }

    unsigned int sbase = (unsigned int)__cvta_generic_to_shared(&sAw[w][0][0]);
    const float4* Ag = g_A4;
    {
        const float4* s0 = Ag + (size_t)b0 * 72 + lane;
        unsigned int d = sbase + lane * 16;
        cp16(d, s0); cp16(d + 32 * 16, s0 + 32);
        if (lane < 8) cp16(d + 64 * 16, s0 + 64);
        cp_commit();
        const float4* s1 = Ag + (size_t)(b0 + 1) * 72 + lane;
        unsigned int d1 = d + 72 * 16;
        cp16(d1, s1); cp16(d1 + 32 * 16, s1 + 32);
        if (lane < 8) cp16(d1 + 64 * 16, s1 + 64);
        cp_commit();
    }
    __syncthreads();

    float pA0, pA1, pA2, pB0, pB1, pB2, pC0, pC1, pC2;
    {
        const float* p = g_vs + ((size_t)b0 * NV + vc0) * 3;
        pA0 = p[0]; pA1 = p[1]; pA2 = p[2];
        const float* q = g_vs + ((size_t)b0 * NV + vc1) * 3;
        pB0 = q[0]; pB1 = q[1]; pB2 = q[2];
        const float* r = g_vs + ((size_t)b0 * NV + vc2) * 3;
        pC0 = r[0]; pC1 = r[1]; pC2 = r[2];
    }

    const float2* wr0 = (const float2*)(sW + tid * WSTR);
    const float2* wr1 = (const float2*)(sW + (tid + CBLK) * WSTR);
    const float2* wr2 = (const float2*)(sW + (tid + 2 * CBLK) * WSTR);

    for (int ib = 0; ib < BPB; ib++) {
        if (ib >= BPB - 2) cp_wait0(); else cp_wait1();
        __syncwarp();

        int cur = ib & 1;
        const ulonglong2* A2 = (const ulonglong2*)&sAw[w][cur][0];

        unsigned long long TA0=0,TA1=0,TA2=0,TA3=0,TA4=0,TA5=0;
        unsigned long long TB0=0,TB1=0,TB2=0,TB3=0,TB4=0,TB5=0;
        unsigned long long TC0=0,TC1=0,TC2=0,TC3=0,TC4=0,TC5=0;
#pragma unroll
        for (int np = 0; np < NJOINT / 2; np++) {
            float2 wA2 = wr0[np];
            float2 wB2 = wr1[np];
            float2 wC2 = wr2[np];
#pragma unroll
            for (int h = 0; h < 2; h++) {
                int n = 2 * np + h;
                float wA = h ? wA2.y : wA2.x;
                float wB = h ? wB2.y : wB2.x;
                float wC = h ? wC2.y : wC2.x;
                unsigned long long wpA, wpB, wpC;
                asm volatile("mov.b64 %0, {%1, %1};" : "=l"(wpA) : "f"(wA));
                asm volatile("mov.b64 %0, {%1, %1};" : "=l"(wpB) : "f"(wB));
                asm volatile("mov.b64 %0, {%1, %1};" : "=l"(wpC) : "f"(wC));
                ulonglong2 a0 = A2[n * 3 + 0];
                ulonglong2 a1 = A2[n * 3 + 1];
                ulonglong2 a2 = A2[n * 3 + 2];
                TA0 = ffma2(wpA, a0.x, TA0); TB0 = ffma2(wpB, a0.x, TB0); TC0 = ffma2(wpC, a0.x, TC0);
                TA1 = ffma2(wpA, a0.y, TA1); TB1 = ffma2(wpB, a0.y, TB1); TC1 = ffma2(wpC, a0.y, TC1);
                TA2 = ffma2(wpA, a1.x, TA2); TB2 = ffma2(wpB, a1.x, TB2); TC2 = ffma2(wpC, a1.x, TC2);
                TA3 = ffma2(wpA, a1.y, TA3); TB3 = ffma2(wpB, a1.y, TB3); TC3 = ffma2(wpC, a1.y, TC3);
                TA4 = ffma2(wpA, a2.x, TA4); TB4 = ffma2(wpB, a2.x, TB4); TC4 = ffma2(wpC, a2.x, TC4);
                TA5 = ffma2(wpA, a2.y, TA5); TB5 = ffma2(wpB, a2.y, TB5); TC5 = ffma2(wpC, a2.y, TC5);
            }
        }

        int b = b0 + ib;
        float tr0 = sTr[ib][0], tr1 = sTr[ib][1], tr2 = sTr[ib][2];

        if (valid0) {
            float t00,t01,t02,t03,t10,t11,t12,t13,t20,t21,t22,t23;
            f2unpack(TA0,t00,t01); f2unpack(TA1,t02,t03);
            f2unpack(TA2,t10,t11); f2unpack(TA3,t12,t13);
            f2unpack(TA4,t20,t21); f2unpack(TA5,t22,t23);
            size_t base = ((size_t)b * NV + v0) * 3;
            out[base+0] = fmaf(t00,pA0, fmaf(t01,pA1, fmaf(t02,pA2, t03 + tr0)));
            out[base+1] = fmaf(t10,pA0, fmaf(t11,pA1, fmaf(t12,pA2, t13 + tr1)));
            out[base+2] = fmaf(t20,pA0, fmaf(t21,pA1, fmaf(t22,pA2, t23 + tr2)));
        }
        if (valid1) {
            float t00,t01,t02,t03,t10,t11,t12,t13,t20,t21,t22,t23;
            f2unpack(TB0,t00,t01); f2unpack(TB1,t02,t03);
            f2unpack(TB2,t10,t11); f2unpack(TB3,t12,t13);
            f2unpack(TB4,t20,t21); f2unpack(TB5,t22,t23);
            size_t base = ((size_t)b * NV + v1) * 3;
            out[base+0] = fmaf(t00,pB0, fmaf(t01,pB1, fmaf(t02,pB2, t03 + tr0)));
            out[base+1] = fmaf(t10,pB0, fmaf(t11,pB1, fmaf(t12,pB2, t13 + tr1)));
            out[base+2] = fmaf(t20,pB0, fmaf(t21,pB1, fmaf(t22,pB2, t23 + tr2)));
        }
        if (valid2) {
            float t00,t01,t02,t03,t10,t11,t12,t13,t20,t21,t22,t23;
            f2unpack(TC0,t00,t01); f2unpack(TC1,t02,t03);
            f2unpack(TC2,t10,t11); f2unpack(TC3,t12,t13);
            f2unpack(TC4,t20,t21); f2unpack(TC5,t22,t23);
            size_t base = ((size_t)b * NV + v2) * 3;
            out[base+0] = fmaf(t00,pC0, fmaf(t01,pC1, fmaf(t02,pC2, t03 + tr0)));
            out[base+1] = fmaf(t10,pC0, fmaf(t11,pC1, fmaf(t12,pC2, t13 + tr1)));
            out[base+2] = fmaf(t20,pC0, fmaf(t21,pC1, fmaf(t22,pC2, t23 + tr2)));
        }

        if (ib + 1 < BPB) {
            const float* p = g_vs + ((size_t)(b + 1) * NV + vc0) * 3;
            pA0 = p[0]; pA1 = p[1]; pA2 = p[2];
            const float* q = g_vs + ((size_t)(b + 1) * NV + vc1) * 3;
            pB0 = q[0]; pB1 = q[1]; pB2 = q[2];
            const float* r = g_vs + ((size_t)(b + 1) * NV + vc2) * 3;
            pC0 = r[0]; pC1 = r[1]; pC2 = r[2];
        }

        if (ib + 2 < BPB) {
            const float4* sn = Ag + (size_t)(b + 2) * 72 + lane;
            unsigned int d = sbase + cur * (72 * 16) + lane * 16;
            cp16(d, sn); cp16(d + 32 * 16, sn + 32);
            if (lane < 8) cp16(d + 64 * 16, sn + 64);
            cp_commit();
        }
    }
}

extern "C" void kernel_launch(void* const* d_in, const int* in_sizes, int n_in,
                              void* d_out, int out_size)
{
    const float* betas      = (const float*)d_in[0];
    const float* body_pose  = (const float*)d_in[1];
    const float* global_or  = (const float*)d_in[2];
    const float* transl     = (const float*)d_in[3];
    const float* shapedirs  = (const float*)d_in[4];
    const float* v_template = (const float*)d_in[5];
    const float* Jr         = (const float*)d_in[6];
    const float* W          = (const float*)d_in[7];
    float* out = (float*)d_out;

    kernelAV<<<NBLKA + VBLKS, 256>>>(shapedirs, v_template, Jr, betas);
    kernelB<<<BATCH / BWARPS, BWARPS * 32>>>(betas, body_pose, global_or, out);
    dim3 gridC((NV + CVERT - 1) / CVERT, NBCH);
    kernelC<<<gridC, CBLK>>>(transl, W, out);
}

// round 17
// speedup vs baseline: 1.1621x; 1.0443x over previous
#include <cuda_runtime.h>
#include <math.h>

#define BATCH 512
#define NV 6890
#define NBETA 10
#define NJOINT 24

#define ATILE 64
#define NBLKA ((NV + ATILE - 1) / ATILE)   // 108

#define CBLK 128         // kernelC threads
#define VPT 3            // vertices per thread
#define CVERT (CBLK*VPT) // 384 vertices per block
#define NBCH 32          // kernelC batch-chunks
#define BPB (BATCH/NBCH) // 16 batches per block
#define WSTR 26          // sW row stride (floats)

#define VBLK 256         // V-path vertices per block (= block size)
#define VB_B 16          // V-path batches per block
#define VCHUNKS ((NV + VBLK - 1) / VBLK)   // 27
#define VBLKS (VCHUNKS * (BATCH / VB_B))   // 864
#define SDSTR 31         // sd smem row stride (odd -> conflict-free)

#define BWF 8            // B-path batches (warps) per block
#define BBLKS (BATCH / BWF)                // 64

#define AV_SMEM 8880     // union smem floats (V needs 8880; B needs 6064; A 3648)

__constant__ int c_parents[NJOINT] = {-1,0,0,0,1,2,3,4,5,6,7,8,9,9,9,12,13,14,16,17,18,19,20,21};

// Device scratch (no allocations allowed)
__device__ float  g_part2[NBLKA][NJOINT][33];
__device__ float  g_tot [NJOINT][33];
__device__ float4 g_A4  [BATCH * NJOINT * 3];
__device__ float  g_vs  [(size_t)BATCH * NV * 3];   // v_shaped scratch (42MB)
__device__ unsigned int g_ctrA;                      // zero-init; self-resetting
__device__ volatile unsigned int g_ready;            // g_tot ready flag; reset by kernelC

// ---- f32x2 packed-math helpers --------------------------------------------
__device__ __forceinline__ void f2unpack(unsigned long long v, float& lo, float& hi) {
    asm("mov.b64 {%0, %1}, %2;" : "=f"(lo), "=f"(hi) : "l"(v));
}
__device__ __forceinline__ unsigned long long ffma2(unsigned long long a,
                                                    unsigned long long b,
                                                    unsigned long long c) {
    unsigned long long d;
    asm("fma.rn.f32x2 %0, %1, %2, %3;" : "=l"(d) : "l"(a), "l"(b), "l"(c));
    return d;
}

// ---- cp.async helpers ------------------------------------------------------
__device__ __forceinline__ void cp16(unsigned int dst, const void* src) {
    asm volatile("cp.async.cg.shared.global [%0], [%1], 16;" :: "r"(dst), "l"(src) : "memory");
}
__device__ __forceinline__ void cp_commit() {
    asm volatile("cp.async.commit_group;" ::: "memory");
}
__device__ __forceinline__ void cp_wait1() {
    asm volatile("cp.async.wait_group 1;" ::: "memory");
}
__device__ __forceinline__ void cp_wait0() {
    asm volatile("cp.async.wait_group 0;" ::: "memory");
}

// ---------------------------------------------------------------------------
// Kernel AVB: fused A (blocks 0..NBLKA-1, last block reduces g_tot and sets
// g_ready), V (middle blocks, coalesced smem staging), and B (last 64 blocks,
// spin on g_ready then per-warp kinematic chains). B-blocks are the tail of
// the grid so they schedule after the wave-1-resident A blocks complete.
// ---------------------------------------------------------------------------
__global__ void __launch_bounds__(256) kernelAVB(
    const float* __restrict__ shapedirs,
    const float* __restrict__ v_template,
    const float* __restrict__ Jr,
    const float* __restrict__ betas,
    const float* __restrict__ body_pose,
    const float* __restrict__ global_or,
    float* __restrict__ d_out)
{
    __shared__ float smem_u[AV_SMEM];
    __shared__ unsigned int sIsLast;

    int tid = threadIdx.x;

    if (blockIdx.x < NBLKA) {
        // ---------------- A body ----------------
        float (*feat)[33] = (float (*)[33])smem_u;
        float (*sJr)[ATILE] = (float (*)[ATILE])(smem_u + ATILE * 33);
        int v0 = blockIdx.x * ATILE;

        for (int idx = tid; idx < ATILE * 33; idx += 256) {
            int v = idx / 33, i = idx % 33;
            int gv = v0 + v;
            float val = 0.f;
            if (gv < NV) val = (i < 3) ? v_template[gv * 3 + i]
                                       : shapedirs[(size_t)gv * 30 + (i - 3)];
            feat[v][i] = val;
        }
        for (int idx = tid; idx < NJOINT * ATILE; idx += 256) {
            int j = idx / ATILE, v = idx % ATILE;
            int gv = v0 + v;
            sJr[j][v] = (gv < NV) ? Jr[j * NV + gv] : 0.f;
        }
        __syncthreads();

        int warp = tid >> 5, lane = tid & 31;
#pragma unroll
        for (int jj = 0; jj < 3; jj++) {
            int j = warp * 3 + jj;
            for (int i = lane; i < 33; i += 32) {
                float a0 = 0.f, a1 = 0.f, a2 = 0.f, a3 = 0.f;
#pragma unroll
                for (int v = 0; v < ATILE; v += 4) {
                    a0 = fmaf(sJr[j][v + 0], feat[v + 0][i], a0);
                    a1 = fmaf(sJr[j][v + 1], feat[v + 1][i], a1);
                    a2 = fmaf(sJr[j][v + 2], feat[v + 2][i], a2);
                    a3 = fmaf(sJr[j][v + 3], feat[v + 3][i], a3);
                }
                g_part2[blockIdx.x][j][i] = (a0 + a1) + (a2 + a3);
            }
        }

        // last-A-block reduction + ready flag
        __threadfence();
        __syncthreads();
        if (tid == 0)
            sIsLast = (atomicAdd(&g_ctrA, 1u) == (unsigned)(NBLKA - 1));
        __syncthreads();
        if (sIsLast) {
            for (int t = tid; t < NJOINT * 33; t += 256) {
                int j = t / 33, i33 = t % 33;
                int src;
                if (i33 % 11 == 0) src = i33 / 11;
                else { int k = i33 / 11, l = i33 % 11 - 1; src = 3 + k * 10 + l; }
                float s0 = 0.f, s1 = 0.f, s2 = 0.f, s3 = 0.f;
                for (int c = 0; c < NBLKA; c += 4) {
                    s0 += g_part2[c + 0][j][src];
                    s1 += g_part2[c + 1][j][src];
                    s2 += g_part2[c + 2][j][src];
                    s3 += g_part2[c + 3][j][src];
                }
                g_tot[j][i33] = (s0 + s1) + (s2 + s3);
            }
            __syncthreads();
            if (tid == 0) {
                g_ctrA = 0;                 // reset for next replay
                __threadfence();
                g_ready = 1;                // release g_tot
            }
        }
    } else if (blockIdx.x < NBLKA + VBLKS) {
        // ---------------- V body (coalesced smem staging) ----------------
        float* sSD = smem_u;                       // 256*31
        float* sVT = smem_u + VBLK * SDSTR;        // 256*3
        float (*sB)[11] = (float (*)[11])(sVT + VBLK * 3);  // 16*11

        int vb = blockIdx.x - NBLKA;
        int vx = vb % VCHUNKS;
        int b0 = (vb / VCHUNKS) * VB_B;
        int v0 = vx * VBLK;
        int nv_blk = min(VBLK, NV - v0);

        {
            const float* src = shapedirs + (size_t)v0 * 30;
            int limit = nv_blk * 30;
            for (int i = tid; i < limit; i += VBLK)
                sSD[(i / 30) * SDSTR + (i % 30)] = src[i];
        }
        {
            const float* src = v_template + (size_t)v0 * 3;
            int limit = nv_blk * 3;
            for (int i = tid; i < limit; i += VBLK)
                sVT[i] = src[i];
        }
        for (int i = tid; i < VB_B * 11; i += VBLK)
            sB[i / 11][i % 11] = betas[(b0 + i / 11) * 11 + i % 11];
        __syncthreads();

        int v = v0 + tid;
        if (v >= NV) return;

        const float* sd = sSD + tid * SDSTR;
        float vt0 = sVT[tid * 3 + 0];
        float vt1 = sVT[tid * 3 + 1];
        float vt2 = sVT[tid * 3 + 2];

#pragma unroll 4
        for (int i = 0; i < VB_B; i++) {
            int b = b0 + i;
            const float* BT = sB[i];
            float be0 = BT[0];
            float q0 = vt0, q1 = vt1, q2 = vt2;
#pragma unroll
            for (int l = 0; l < NBETA; l++) {
                float bl = BT[1 + l];
                q0 = fmaf(bl, sd[l],      q0);
                q1 = fmaf(bl, sd[10 + l], q1);
                q2 = fmaf(bl, sd[20 + l], q2);
            }
            size_t base = ((size_t)b * NV + v) * 3;
            g_vs[base + 0] = q0 * be0;
            g_vs[base + 1] = q1 * be0;
            g_vs[base + 2] = q2 * be0;
        }
    } else {
        // ---------------- B body (8 batches, 1 warp each) ----------------
        // smem carve: sTot 792 | sB8 88 | sLoc 2304 | sWorld 2304 | sJ 576
        float (*sTot)[33]        = (float (*)[33])smem_u;
        float (*sB8)[11]         = (float (*)[11])(smem_u + 792);
        float (*sLoc)[NJOINT][12]   = (float (*)[NJOINT][12])(smem_u + 880);
        float (*sWorld)[NJOINT][12] = (float (*)[NJOINT][12])(smem_u + 3184);
        float (*sJ)[NJOINT][3]      = (float (*)[NJOINT][3])(smem_u + 5488);

        int wid = tid >> 5;
        int lane = tid & 31;
        int b = (blockIdx.x - NBLKA - VBLKS) * BWF + wid;

        // wait for g_tot (set by last A block; A blocks are wave-1 resident)
        if (tid == 0) {
            while (g_ready == 0u) __nanosleep(128);
        }
        __syncthreads();
        __threadfence();

        for (int idx = tid; idx < NJOINT * 33; idx += 256)
            ((float*)sTot)[idx] = ((const float*)g_tot)[idx];
        if (lane < 11) sB8[wid][lane] = betas[b * 11 + lane];
        __syncthreads();

        if (lane < NJOINT) {
            int j = lane;
            float s0 = sB8[wid][0];
#pragma unroll
            for (int k = 0; k < 3; k++) {
                float val = sTot[j][k * 11];
#pragma unroll
                for (int l = 0; l < NBETA; l++)
                    val += sB8[wid][1 + l] * sTot[j][k * 11 + 1 + l];
                sJ[wid][j][k] = val * s0;
            }
        }
        __syncwarp();

        if (lane < NJOINT) {
            int j = lane;
            float r0, r1, r2;
            if (j == 0) {
                r0 = global_or[b * 3 + 0]; r1 = global_or[b * 3 + 1]; r2 = global_or[b * 3 + 2];
            } else {
                const float* pp = body_pose + b * 69 + (j - 1) * 3;
                r0 = pp[0]; r1 = pp[1]; r2 = pp[2];
            }
            float a0 = r0 + 1e-8f, a1 = r1 + 1e-8f, a2 = r2 + 1e-8f;
            float angle = __fsqrt_rn(a0 * a0 + a1 * a1 + a2 * a2);
            float inv = __frcp_rn(angle);
            float rx = r0 * inv, ry = r1 * inv, rz = r2 * inv;
            float c = __cosf(angle), s = __sinf(angle), t = 1.f - c;
            sLoc[wid][j][0]  = 1.f - t * (ry * ry + rz * rz);
            sLoc[wid][j][1]  = -s * rz + t * rx * ry;
            sLoc[wid][j][2]  =  s * ry + t * rx * rz;
            sLoc[wid][j][4]  =  s * rz + t * rx * ry;
            sLoc[wid][j][5]  = 1.f - t * (rx * rx + rz * rz);
            sLoc[wid][j][6]  = -s * rx + t * ry * rz;
            sLoc[wid][j][8]  = -s * ry + t * rx * rz;
            sLoc[wid][j][9]  =  s * rx + t * ry * rz;
            sLoc[wid][j][10] = 1.f - t * (rx * rx + ry * ry);
            int p = c_parents[j];
#pragma unroll
            for (int k = 0; k < 3; k++)
                sLoc[wid][j][k * 4 + 3] = (p < 0) ? sJ[wid][j][k]
                                                  : (sJ[wid][j][k] - sJ[wid][p][k]);
        }
        __syncwarp();

        if (lane < 12) sWorld[wid][0][lane] = sLoc[wid][0][lane];
        __syncwarp();
        for (int j = 1; j < NJOINT; j += 2) {
            int jj = j + (lane >= 12 ? 1 : 0);
            int l12 = (lane >= 12) ? (lane - 12) : lane;
            if (lane < 24 && jj < NJOINT) {
                int r = l12 >> 2, cc = l12 & 3;
                int p = c_parents[jj];
                float val = sWorld[wid][p][r * 4 + 0] * sLoc[wid][jj][0 * 4 + cc]
                          + sWorld[wid][p][r * 4 + 1] * sLoc[wid][jj][1 * 4 + cc]
                          + sWorld[wid][p][r * 4 + 2] * sLoc[wid][jj][2 * 4 + cc];
                if (cc == 3) val += sWorld[wid][p][r * 4 + 3];
                sWorld[wid][jj][l12] = val;
            }
            __syncwarp();
        }

        float* Jout = d_out + (size_t)BATCH * NV * 3;
        if (lane < NJOINT) {
            int j = lane;
            float jx = sJ[wid][j][0], jy = sJ[wid][j][1], jz = sJ[wid][j][2];
            float* Aout = (float*)g_A4 + (size_t)b * 288 + j * 12;
#pragma unroll
            for (int r = 0; r < 3; r++) {
                float m0 = sWorld[wid][j][r * 4 + 0];
                float m1 = sWorld[wid][j][r * 4 + 1];
                float m2 = sWorld[wid][j][r * 4 + 2];
                float m3 = sWorld[wid][j][r * 4 + 3];
                Jout[(size_t)b * NJOINT * 3 + j * 3 + r] = m3;
                Aout[r * 4 + 0] = m0;
                Aout[r * 4 + 1] = m1;
                Aout[r * 4 + 2] = m2;
                Aout[r * 4 + 3] = m3 - (m0 * jx + m1 * jy + m2 * jz);
            }
        }
    }
}

// ---------------------------------------------------------------------------
// Kernel C: LBS, VPT=3 — A-broadcast LDS amortized over 3 vertices.
// Block (0,0) also resets g_ready for the next graph replay.
// ---------------------------------------------------------------------------
__global__ void __launch_bounds__(CBLK, 4) kernelC(
    const float* __restrict__ transl,      // [B,3]
    const float* __restrict__ W,           // [V,24]
    float* __restrict__ out)               // verts [B,V,3]
{
    __shared__ float4 sAw[CBLK / 32][2][NJOINT * 3];
    __shared__ float  sTr[BPB][3];
    __shared__ float  sW[CVERT * WSTR];

    int tid = threadIdx.x;
    int lane = tid & 31;
    int w = tid >> 5;
    int b0 = blockIdx.y * BPB;

    if (blockIdx.x == 0 && blockIdx.y == 0 && tid == 0)
        g_ready = 0;   // stream-ordered after AVB completed

    int v0 = blockIdx.x * CVERT + tid;
    int v1 = v0 + CBLK;
    int v2 = v0 + 2 * CBLK;
    bool valid0 = (v0 < NV), valid1 = (v1 < NV), valid2 = (v2 < NV);
    int vc0 = valid0 ? v0 : (NV - 1);
    int vc1 = valid1 ? v1 : (NV - 1);
    int vc2 = valid2 ? v2 : (NV - 1);

    for (int idx = tid; idx < BPB * 3; idx += CBLK)
        sTr[idx / 3][idx % 3] = transl[(b0 + idx / 3) * 3 + idx % 3];

    {
        const float4* Wp0 = (const float4*)(W + (size_t)vc0 * NJOINT);
        const float4* Wp1 = (const float4*)(W + (size_t)vc1 * NJOINT);
        const float4* Wp2 = (const float4*)(W + (size_t)vc2 * NJOINT);
        float* r0 = sW + tid * WSTR;
        float* r1 = sW + (tid + CBLK) * WSTR;
        float* r2 = sW + (tid + 2 * CBLK) * WSTR;
#pragma unroll
        for (int q = 0; q < 6; q++) {
            float4 t4 = Wp0[q];
            r0[4*q+0] = t4.x; r0[4*q+1] = t4.y; r0[4*q+2] = t4.z; r0[4*q+3] = t4.w;
            float4 u4 = Wp1[q];
            r1[4*q+0] = u4.x; r1[4*q+1] = u4.y; r1[4*q+2] = u4.z; r1[4*q+3] = u4.w;
            float4 s4 = Wp2[q];
            r2[4*q+0] = s4.x; r2[4*q+1] = s4.y; r2[4*q+2] = s4.z; r2[4*q+3] = s4.w;
        }
    }

    unsigned int sbase = (unsigned int)__cvta_generic_to_shared(&sAw[w][0][0]);
    const float4* Ag = g_A4;
    {
        const float4* s0 = Ag + (size_t)b0 * 72 + lane;
        unsigned int d = sbase + lane * 16;
        cp16(d, s0); cp16(d + 32 * 16, s0 + 32);
        if (lane < 8) cp16(d + 64 * 16, s0 + 64);
        cp_commit();
        const float4* s1 = Ag + (size_t)(b0 + 1) * 72 + lane;
        unsigned int d1 = d + 72 * 16;
        cp16(d1, s1); cp16(d1 + 32 * 16, s1 + 32);
        if (lane < 8) cp16(d1 + 64 * 16, s1 + 64);
        cp_commit();
    }
    __syncthreads();

    float pA0, pA1, pA2, pB0, pB1, pB2, pC0, pC1, pC2;
    {
        const float* p = g_vs + ((size_t)b0 * NV + vc0) * 3;
        pA0 = p[0]; pA1 = p[1]; pA2 = p[2];
        const float* q = g_vs + ((size_t)b0 * NV + vc1) * 3;
        pB0 = q[0]; pB1 = q[1]; pB2 = q[2];
        const float* r = g_vs + ((size_t)b0 * NV + vc2) * 3;
        pC0 = r[0]; pC1 = r[1]; pC2 = r[2];
    }

    const float2* wr0 = (const float2*)(sW + tid * WSTR);
    const float2* wr1 = (const float2*)(sW + (tid + CBLK) * WSTR);
    const float2* wr2 = (const float2*)(sW + (tid + 2 * CBLK) * WSTR);

    for (int ib = 0; ib < BPB; ib++) {
        if (ib >= BPB - 2) cp_wait0(); else cp_wait1();
        __syncwarp();

        int cur = ib & 1;
        const ulonglong2* A2 = (const ulonglong2*)&sAw[w][cur][0];

        unsigned long long TA0=0,TA1=0,TA2=0,TA3=0,TA4=0,TA5=0;
        unsigned long long TB0=0,TB1=0,TB2=0,TB3=0,TB4=0,TB5=0;
        unsigned long long TC0=0,TC1=0,TC2=0,TC3=0,TC4=0,TC5=0;
#pragma unroll
        for (int np = 0; np < NJOINT / 2; np++) {
            float2 wA2 = wr0[np];
            float2 wB2 = wr1[np];
            float2 wC2 = wr2[np];
#pragma unroll
            for (int h = 0; h < 2; h++) {
                int n = 2 * np + h;
                float wA = h ? wA2.y : wA2.x;
                float wB = h ? wB2.y : wB2.x;
                float wC = h ? wC2.y : wC2.x;
                unsigned long long wpA, wpB, wpC;
                asm volatile("mov.b64 %0, {%1, %1};" : "=l"(wpA) : "f"(wA));
                asm volatile("mov.b64 %0, {%1, %1};" : "=l"(wpB) : "f"(wB));
                asm volatile("mov.b64 %0, {%1, %1};" : "=l"(wpC) : "f"(wC));
                ulonglong2 a0 = A2[n * 3 + 0];
                ulonglong2 a1 = A2[n * 3 + 1];
                ulonglong2 a2 = A2[n * 3 + 2];
                TA0 = ffma2(wpA, a0.x, TA0); TB0 = ffma2(wpB, a0.x, TB0); TC0 = ffma2(wpC, a0.x, TC0);
                TA1 = ffma2(wpA, a0.y, TA1); TB1 = ffma2(wpB, a0.y, TB1); TC1 = ffma2(wpC, a0.y, TC1);
                TA2 = ffma2(wpA, a1.x, TA2); TB2 = ffma2(wpB, a1.x, TB2); TC2 = ffma2(wpC, a1.x, TC2);
                TA3 = ffma2(wpA, a1.y, TA3); TB3 = ffma2(wpB, a1.y, TB3); TC3 = ffma2(wpC, a1.y, TC3);
                TA4 = ffma2(wpA, a2.x, TA4); TB4 = ffma2(wpB, a2.x, TB4); TC4 = ffma2(wpC, a2.x, TC4);
                TA5 = ffma2(wpA, a2.y, TA5); TB5 = ffma2(wpB, a2.y, TB5); TC5 = ffma2(wpC, a2.y, TC5);
            }
        }

        int b = b0 + ib;
        float tr0 = sTr[ib][0], tr1 = sTr[ib][1], tr2 = sTr[ib][2];

        if (valid0) {
            float t00,t01,t02,t03,t10,t11,t12,t13,t20,t21,t22,t23;
            f2unpack(TA0,t00,t01); f2unpack(TA1,t02,t03);
            f2unpack(TA2,t10,t11); f2unpack(TA3,t12,t13);
            f2unpack(TA4,t20,t21); f2unpack(TA5,t22,t23);
            size_t base = ((size_t)b * NV + v0) * 3;
            out[base+0] = fmaf(t00,pA0, fmaf(t01,pA1, fmaf(t02,pA2, t03 + tr0)));
            out[base+1] = fmaf(t10,pA0, fmaf(t11,pA1, fmaf(t12,pA2, t13 + tr1)));
            out[base+2] = fmaf(t20,pA0, fmaf(t21,pA1, fmaf(t22,pA2, t23 + tr2)));
        }
        if (valid1) {
            float t00,t01,t02,t03,t10,t11,t12,t13,t20,t21,t22,t23;
            f2unpack(TB0,t00,t01); f2unpack(TB1,t02,t03);
            f2unpack(TB2,t10,t11); f2unpack(TB3,t12,t13);
            f2unpack(TB4,t20,t21); f2unpack(TB5,t22,t23);
            size_t base = ((size_t)b * NV + v1) * 3;
            out[base+0] = fmaf(t00,pB0, fmaf(t01,pB1, fmaf(t02,pB2, t03 + tr0)));
            out[base+1] = fmaf(t10,pB0, fmaf(t11,pB1, fmaf(t12,pB2, t13 + tr1)));
            out[base+2] = fmaf(t20,pB0, fmaf(t21,pB1, fmaf(t22,pB2, t23 + tr2)));
        }
        if (valid2) {
            float t00,t01,t02,t03,t10,t11,t12,t13,t20,t21,t22,t23;
            f2unpack(TC0,t00,t01); f2unpack(TC1,t02,t03);
            f2unpack(TC2,t10,t11); f2unpack(TC3,t12,t13);
            f2unpack(TC4,t20,t21); f2unpack(TC5,t22,t23);
            size_t base = ((size_t)b * NV + v2) * 3;
            out[base+0] = fmaf(t00,pC0, fmaf(t01,pC1, fmaf(t02,pC2, t03 + tr0)));
            out[base+1] = fmaf(t10,pC0, fmaf(t11,pC1, fmaf(t12,pC2, t13 + tr1)));
            out[base+2] = fmaf(t20,pC0, fmaf(t21,pC1, fmaf(t22,pC2, t23 + tr2)));
        }

        if (ib + 1 < BPB) {
            const float* p = g_vs + ((size_t)(b + 1) * NV + vc0) * 3;
            pA0 = p[0]; pA1 = p[1]; pA2 = p[2];
            const float* q = g_vs + ((size_t)(b + 1) * NV + vc1) * 3;
            pB0 = q[0]; pB1 = q[1]; pB2 = q[2];
            const float* r = g_vs + ((size_t)(b + 1) * NV + vc2) * 3;
            pC0 = r[0]; pC1 = r[1]; pC2 = r[2];
        }

        if (ib + 2 < BPB) {
            const float4* sn = Ag + (size_t)(b + 2) * 72 + lane;
            unsigned int d = sbase + cur * (72 * 16) + lane * 16;
            cp16(d, sn); cp16(d + 32 * 16, sn + 32);
            if (lane < 8) cp16(d + 64 * 16, sn + 64);
            cp_commit();
        }
    }
}

extern "C" void kernel_launch(void* const* d_in, const int* in_sizes, int n_in,
                              void* d_out, int out_size)
{
    const float* betas      = (const float*)d_in[0];
    const float* body_pose  = (const float*)d_in[1];
    const float* global_or  = (const float*)d_in[2];
    const float* transl     = (const float*)d_in[3];
    const float* shapedirs  = (const float*)d_in[4];
    const float* v_template = (const float*)d_in[5];
    const float* Jr         = (const float*)d_in[6];
    const float* W          = (const float*)d_in[7];
    float* out = (float*)d_out;

    kernelAVB<<<NBLKA + VBLKS + BBLKS, 256>>>(shapedirs, v_template, Jr,
                                              betas, body_pose, global_or, out);
    dim3 gridC((NV + CVERT - 1) / CVERT, NBCH);
    kernelC<<<gridC, CBLK>>>(transl, W, out);
}